// round 9
// baseline (speedup 1.0000x reference)
#include <cuda_runtime.h>
#include <cuda_bf16.h>
#include <cuda_fp16.h>
#include <math.h>
#include <stdint.h>

// Problem constants
#define B_    2
#define D_    5
#define H_    32
#define W_    32
#define C_    256
#define NH_   8
#define NL_   5
#define NP_   16
#define HD_   32
#define HW_   (H_*W_)          // 1024
#define LQ_   (D_*HW_)         // 5120
#define M_    (B_*LQ_)         // 10240
#define MLP_H_ 1024
#define PTS_  (NL_*NP_)        // 80
#define NPROJ_ 2176            // 256 (val) + 1280 (off) + 640 (attn)
#define LVL_STRIDE_ (NH_*HW_*HD_)   // elements per level (head-major val)

// ---------------- scratch (device globals; no allocation) ----------------
__device__ __nv_bfloat16 g_q   [M_*C_];
__device__ __nv_bfloat16 g_valh[B_*NL_*NH_*HW_*HD_ + 64]; // head-major (+pad)
__device__ float         g_off [M_*NH_*PTS_*2];
__device__ float         g_attn[M_*NH_*PTS_];
__device__ __nv_bfloat16 g_samp[M_*C_];
__device__ __nv_bfloat16 g_h   [M_*C_];
__device__ __nv_bfloat16 g_mlp [M_*MLP_H_];
// transposed bf16 weights [N,K]
__device__ __nv_bfloat16 g_wproj[NPROJ_*C_];
__device__ __nv_bfloat16 g_wout [C_*C_];
__device__ __nv_bfloat16 g_wfc1 [MLP_H_*C_];
__device__ __nv_bfloat16 g_wfc2 [C_*MLP_H_];

__device__ __forceinline__ uint32_t smem_u32(const void* p) {
    uint32_t a;
    asm("{ .reg .u64 t; cvta.to.shared.u64 t, %1; cvt.u32.u64 %0, t; }" : "=r"(a) : "l"(p));
    return a;
}
__device__ __forceinline__ void cp_async16(uint32_t s, const void* g) {
    asm volatile("cp.async.cg.shared.global [%0], [%1], 16;" :: "r"(s), "l"(g) : "memory");
}
__device__ __forceinline__ void cp_commit() {
    asm volatile("cp.async.commit_group;" ::: "memory");
}
__device__ __forceinline__ void cp_wait1() {
    asm volatile("cp.async.wait_group 1;" ::: "memory");
}
__device__ __forceinline__ void ldmx4(uint32_t& r0, uint32_t& r1, uint32_t& r2, uint32_t& r3, uint32_t a) {
    asm volatile("ldmatrix.sync.aligned.m8n8.x4.shared.b16 {%0,%1,%2,%3}, [%4];"
                 : "=r"(r0), "=r"(r1), "=r"(r2), "=r"(r3) : "r"(a));
}
__device__ __forceinline__ void ldmx4t(uint32_t& r0, uint32_t& r1, uint32_t& r2, uint32_t& r3, uint32_t a) {
    asm volatile("ldmatrix.sync.aligned.m8n8.x4.trans.shared.b16 {%0,%1,%2,%3}, [%4];"
                 : "=r"(r0), "=r"(r1), "=r"(r2), "=r"(r3) : "r"(a));
}
__device__ __forceinline__ void ldmx2(uint32_t& r0, uint32_t& r1, uint32_t a) {
    asm volatile("ldmatrix.sync.aligned.m8n8.x2.shared.b16 {%0,%1}, [%2];"
                 : "=r"(r0), "=r"(r1) : "r"(a));
}
__device__ __forceinline__ void mma_bf16(float* c, const uint32_t* a, const uint32_t* b) {
    asm volatile(
        "mma.sync.aligned.m16n8k16.row.col.f32.bf16.bf16.f32 "
        "{%0,%1,%2,%3}, {%4,%5,%6,%7}, {%8,%9}, {%0,%1,%2,%3};"
        : "+f"(c[0]), "+f"(c[1]), "+f"(c[2]), "+f"(c[3])
        : "r"(a[0]), "r"(a[1]), "r"(a[2]), "r"(a[3]), "r"(b[0]), "r"(b[1]));
}

// ---------------------------------------------------------------------------
// LayerNorm: block(256) per row, writes bf16
// ---------------------------------------------------------------------------
__global__ void ln_kernel(const float* __restrict__ x,
                          const float* __restrict__ g,
                          const float* __restrict__ b,
                          __nv_bfloat16* __restrict__ out)
{
    int row = blockIdx.x;
    int c   = threadIdx.x;
    float v = x[(size_t)row*C_ + c];
    float sum = v, sq = v*v;
    #pragma unroll
    for (int o = 16; o > 0; o >>= 1) {
        sum += __shfl_xor_sync(0xffffffffu, sum, o);
        sq  += __shfl_xor_sync(0xffffffffu, sq , o);
    }
    __shared__ float s1[8], s2[8];
    int w = c >> 5, l = c & 31;
    if (l == 0) { s1[w] = sum; s2[w] = sq; }
    __syncthreads();
    sum = 0.f; sq = 0.f;
    #pragma unroll
    for (int i = 0; i < 8; i++) { sum += s1[i]; sq += s2[i]; }
    float m   = sum * (1.f / C_);
    float var = sq  * (1.f / C_) - m*m;
    float inv = rsqrtf(var + 1e-5f);
    out[(size_t)row*C_ + c] = __float2bfloat16((v - m) * inv * g[c] + b[c]);
}

// ---------------------------------------------------------------------------
// Fused weight transpose+convert (1120 tiles of 32x32)
// ---------------------------------------------------------------------------
__global__ void tcvt6_kernel(
    const float* __restrict__ s0, const float* __restrict__ s1,
    const float* __restrict__ s2, const float* __restrict__ s3,
    const float* __restrict__ s4, const float* __restrict__ s5,
    __nv_bfloat16* __restrict__ dproj,
    __nv_bfloat16* __restrict__ d3,
    __nv_bfloat16* __restrict__ d4, __nv_bfloat16* __restrict__ d5)
{
    int t = blockIdx.x;
    const float* src; __nv_bfloat16* dst; int K, N;
    if      (t < 64)  { src=s0; dst=dproj;              K=256;  N=256;          }
    else if (t < 384) { src=s1; dst=dproj + 256*256;    K=256;  N=1280; t-=64;  }
    else if (t < 544) { src=s2; dst=dproj + 1536*256;   K=256;  N=640;  t-=384; }
    else if (t < 608) { src=s3; dst=d3;                 K=256;  N=256;  t-=544; }
    else if (t < 864) { src=s4; dst=d4;                 K=256;  N=1024; t-=608; }
    else              { src=s5; dst=d5;                 K=1024; N=256;  t-=864; }
    int bx = t % (N/32), by = t / (N/32);

    __shared__ float tl[32][33];
    int k = by*32 + threadIdx.y;
    int n = bx*32 + threadIdx.x;
    tl[threadIdx.y][threadIdx.x] = src[(size_t)k*N + n];
    __syncthreads();
    int on = bx*32 + threadIdx.y;
    int ok = by*32 + threadIdx.x;
    dst[(size_t)on*K + ok] = __float2bfloat16(tl[threadIdx.x][threadIdx.y]);
}

// ---------------------------------------------------------------------------
// GEMM config: 128x128 tile, BK=32, 256 thr, 8 warps.
// ---------------------------------------------------------------------------
#define BK_ 32
#define LDS_ 40

template<int ACT, int RES, int BF16OUT>
__global__ void __launch_bounds__(256) gemm_hmma(
    int M, int N, int K,
    const __nv_bfloat16* __restrict__ A,
    const __nv_bfloat16* __restrict__ Bw,
    const float* __restrict__ bias,
    const float* __restrict__ res,
    float* __restrict__ Cf,
    __nv_bfloat16* __restrict__ Cb)
{
    __shared__ __nv_bfloat16 As[2][128][LDS_];
    __shared__ __nv_bfloat16 Bs[2][128][LDS_];

    int tid  = threadIdx.x;
    int lane = tid & 31;
    int wid  = tid >> 5;
    int wm   = wid & 3;
    int wn   = wid >> 2;

    int brow = blockIdx.y * 128;
    int bcol = blockIdx.x * 128;
    const int NIT = K / BK_;

    int r0c = tid >> 2;
    int c0c = (tid & 3) * 8;

    auto load_tile = [&](int it, int buf) {
        const __nv_bfloat16* ag = A  + (size_t)(brow + r0c) * K + it*BK_ + c0c;
        cp_async16(smem_u32(&As[buf][r0c][c0c]),      ag);
        cp_async16(smem_u32(&As[buf][r0c+64][c0c]),   ag + (size_t)64*K);
        const __nv_bfloat16* bg = Bw + (size_t)(bcol + r0c) * K + it*BK_ + c0c;
        cp_async16(smem_u32(&Bs[buf][r0c][c0c]),      bg);
        cp_async16(smem_u32(&Bs[buf][r0c+64][c0c]),   bg + (size_t)64*K);
    };

    float acc[2][8][4];
    #pragma unroll
    for (int mi = 0; mi < 2; mi++)
        #pragma unroll
        for (int ni = 0; ni < 8; ni++)
            #pragma unroll
            for (int k = 0; k < 4; k++) acc[mi][ni][k] = 0.f;

    load_tile(0, 0); cp_commit();
    load_tile(1, 1); cp_commit();

    for (int it = 0; it < NIT; ++it) {
        cp_wait1();
        __syncthreads();
        int cur = it & 1;

        #pragma unroll
        for (int kk = 0; kk < 2; kk++) {
            int k0 = kk * 16;
            uint32_t af[2][4], bfr[8][2];
            #pragma unroll
            for (int mi = 0; mi < 2; mi++) {
                uint32_t addr = smem_u32(&As[cur][wm*32 + mi*16 + (lane & 15)]
                                                [k0 + (lane >> 4) * 8]);
                ldmx4(af[mi][0], af[mi][1], af[mi][2], af[mi][3], addr);
            }
            #pragma unroll
            for (int ni = 0; ni < 8; ni++) {
                uint32_t addr = smem_u32(&Bs[cur][wn*64 + ni*8 + (lane & 7)]
                                                [k0 + ((lane >> 3) & 1) * 8]);
                ldmx2(bfr[ni][0], bfr[ni][1], addr);
            }
            #pragma unroll
            for (int mi = 0; mi < 2; mi++)
                #pragma unroll
                for (int ni = 0; ni < 8; ni++)
                    mma_bf16(acc[mi][ni], af[mi], bfr[ni]);
        }
        __syncthreads();
        if (it + 2 < NIT) load_tile(it + 2, cur);
        cp_commit();
    }

    int gq = lane >> 2, tq = lane & 3;
    #pragma unroll
    for (int mi = 0; mi < 2; mi++) {
        #pragma unroll
        for (int half = 0; half < 2; half++) {
            int row = brow + wm*32 + mi*16 + half*8 + gq;
            #pragma unroll
            for (int ni = 0; ni < 8; ni++) {
                int col = bcol + wn*64 + ni*8 + tq*2;
                float v0 = acc[mi][ni][half*2 + 0] + bias[col];
                float v1 = acc[mi][ni][half*2 + 1] + bias[col + 1];
                if (ACT == 1) {
                    v0 = 0.5f * v0 * (1.f + erff(v0 * 0.70710678118654752f));
                    v1 = 0.5f * v1 * (1.f + erff(v1 * 0.70710678118654752f));
                }
                if (RES) {
                    const float2 r2 = *(const float2*)&res[(size_t)row * N + col];
                    v0 += r2.x; v1 += r2.y;
                }
                if (BF16OUT) {
                    __nv_bfloat162 o;
                    o.x = __float2bfloat16(v0);
                    o.y = __float2bfloat16(v1);
                    *(__nv_bfloat162*)&Cb[(size_t)row * N + col] = o;
                } else {
                    float2 o; o.x = v0; o.y = v1;
                    *(float2*)&Cf[(size_t)row * N + col] = o;
                }
            }
        }
    }
}

// ---------------------------------------------------------------------------
// Fused projection GEMM: A[M,256] @ Wproj[2176,256]^T, routed epilogue.
// ---------------------------------------------------------------------------
__global__ void __launch_bounds__(256) gemm_proj(
    const __nv_bfloat16* __restrict__ A,
    const float* __restrict__ bv,
    const float* __restrict__ bo,
    const float* __restrict__ ba)
{
    const int K = C_;
    __shared__ __nv_bfloat16 As[2][128][LDS_];
    __shared__ __nv_bfloat16 Bs[2][128][LDS_];

    int tid  = threadIdx.x;
    int lane = tid & 31;
    int wid  = tid >> 5;
    int wm   = wid & 3;
    int wn   = wid >> 2;

    int brow = blockIdx.y * 128;
    int bcol = blockIdx.x * 128;
    const int NIT = K / BK_;

    int r0c = tid >> 2;
    int c0c = (tid & 3) * 8;
    const __nv_bfloat16* Bw = g_wproj;

    auto load_tile = [&](int it, int buf) {
        const __nv_bfloat16* ag = A  + (size_t)(brow + r0c) * K + it*BK_ + c0c;
        cp_async16(smem_u32(&As[buf][r0c][c0c]),      ag);
        cp_async16(smem_u32(&As[buf][r0c+64][c0c]),   ag + (size_t)64*K);
        const __nv_bfloat16* bg = Bw + (size_t)(bcol + r0c) * K + it*BK_ + c0c;
        cp_async16(smem_u32(&Bs[buf][r0c][c0c]),      bg);
        cp_async16(smem_u32(&Bs[buf][r0c+64][c0c]),   bg + (size_t)64*K);
    };

    float acc[2][8][4];
    #pragma unroll
    for (int mi = 0; mi < 2; mi++)
        #pragma unroll
        for (int ni = 0; ni < 8; ni++)
            #pragma unroll
            for (int k = 0; k < 4; k++) acc[mi][ni][k] = 0.f;

    load_tile(0, 0); cp_commit();
    load_tile(1, 1); cp_commit();

    for (int it = 0; it < NIT; ++it) {
        cp_wait1();
        __syncthreads();
        int cur = it & 1;
        #pragma unroll
        for (int kk = 0; kk < 2; kk++) {
            int k0 = kk * 16;
            uint32_t af[2][4], bfr[8][2];
            #pragma unroll
            for (int mi = 0; mi < 2; mi++) {
                uint32_t addr = smem_u32(&As[cur][wm*32 + mi*16 + (lane & 15)]
                                                [k0 + (lane >> 4) * 8]);
                ldmx4(af[mi][0], af[mi][1], af[mi][2], af[mi][3], addr);
            }
            #pragma unroll
            for (int ni = 0; ni < 8; ni++) {
                uint32_t addr = smem_u32(&Bs[cur][wn*64 + ni*8 + (lane & 7)]
                                                [k0 + ((lane >> 3) & 1) * 8]);
                ldmx2(bfr[ni][0], bfr[ni][1], addr);
            }
            #pragma unroll
            for (int mi = 0; mi < 2; mi++)
                #pragma unroll
                for (int ni = 0; ni < 8; ni++)
                    mma_bf16(acc[mi][ni], af[mi], bfr[ni]);
        }
        __syncthreads();
        if (it + 2 < NIT) load_tile(it + 2, cur);
        cp_commit();
    }

    int gq = lane >> 2, tq = lane & 3;
    if (bcol < 256) {
        #pragma unroll
        for (int mi = 0; mi < 2; mi++)
            #pragma unroll
            for (int half = 0; half < 2; half++) {
                int row = brow + wm*32 + mi*16 + half*8 + gq;
                int bb  = row / LQ_;
                int rem = row - bb*LQ_;
                int d   = rem >> 10;
                int pix = rem & 1023;
                size_t tokbase = ((size_t)((bb*NL_ + d)*NH_) * HW_ + pix) * HD_;
                #pragma unroll
                for (int ni = 0; ni < 8; ni++) {
                    int col = bcol + wn*64 + ni*8 + tq*2;
                    int h  = col >> 5;
                    int hd = col & 31;
                    float v0 = acc[mi][ni][half*2 + 0] + bv[col];
                    float v1 = acc[mi][ni][half*2 + 1] + bv[col + 1];
                    __nv_bfloat162 o;
                    o.x = __float2bfloat16(v0);
                    o.y = __float2bfloat16(v1);
                    *(__nv_bfloat162*)&g_valh[tokbase + (size_t)h*HW_*HD_ + hd] = o;
                }
            }
    } else if (bcol < 1536) {
        #pragma unroll
        for (int mi = 0; mi < 2; mi++)
            #pragma unroll
            for (int half = 0; half < 2; half++) {
                int row = brow + wm*32 + mi*16 + half*8 + gq;
                #pragma unroll
                for (int ni = 0; ni < 8; ni++) {
                    int col = bcol - 256 + wn*64 + ni*8 + tq*2;
                    float2 o;
                    o.x = acc[mi][ni][half*2 + 0] + bo[col];
                    o.y = acc[mi][ni][half*2 + 1] + bo[col + 1];
                    *(float2*)&g_off[(size_t)row * 1280 + col] = o;
                }
            }
    } else {
        #pragma unroll
        for (int mi = 0; mi < 2; mi++)
            #pragma unroll
            for (int half = 0; half < 2; half++) {
                int row = brow + wm*32 + mi*16 + half*8 + gq;
                #pragma unroll
                for (int ni = 0; ni < 8; ni++) {
                    int col = bcol - 1536 + wn*64 + ni*8 + tq*2;
                    float2 o;
                    o.x = acc[mi][ni][half*2 + 0] + ba[col];
                    o.y = acc[mi][ni][half*2 + 1] + ba[col + 1];
                    *(float2*)&g_attn[(size_t)row * 640 + col] = o;
                }
            }
    }
}

// ---------------------------------------------------------------------------
// FUSED softmax + prep + TENSOR-CORE gather. Block = token, warp = head.
// Phase 1: softmax; per point store 4 corner byte-offsets (u32, level folded:
//   l<<19 | pix<<6) and 4 bf16 weights (attn prob & validity folded) in smem.
// Phase 2: out[32ch] = sum over 320 corner-rows of w_i * V[i][32ch], computed
//   as 20 chained mma.m16n8k16: stage 16 rows (64B each) via LDG.128+STS.128,
//   B-frags via ldmatrix.x4.trans, weights in A-frag row 0, f32 accum in D
//   row 0. No shfl reduction needed. Lanes 0-3 store the result.
// ---------------------------------------------------------------------------
#define STW_ 40                 // stage row stride in bf16 (80 B, conflict-free ldmatrix)
#define STAGE_B_ (16*STW_*2)    // bytes per stage buffer (1280)

__global__ void __launch_bounds__(256) sample_fused_kernel(const float* __restrict__ ref)
{
    __shared__ uint32_t      s_off[NH_][324];
    __shared__ __nv_bfloat16 s_w  [NH_][324];
    __shared__ __nv_bfloat16 s_stage[NH_][2][16*STW_];

    int r    = blockIdx.x;
    int h    = threadIdx.x >> 5;
    int lane = threadIdx.x & 31;
    int b    = r / LQ_;

    // ---- Phase 1: softmax + record build (corner-row order: pt*4 + corner) ----
    {
        const float* p = g_attn + (size_t)r * (NH_*PTS_) + h * PTS_;
        float v0 = p[lane];
        float v1 = p[lane + 32];
        float v2 = (lane < 16) ? p[lane + 64] : -1e30f;
        float mx = fmaxf(v0, fmaxf(v1, v2));
        #pragma unroll
        for (int o = 16; o > 0; o >>= 1) mx = fmaxf(mx, __shfl_xor_sync(0xffffffffu, mx, o));
        float e0 = expf(v0 - mx);
        float e1 = expf(v1 - mx);
        float e2 = (lane < 16) ? expf(v2 - mx) : 0.f;
        float s = e0 + e1 + e2;
        #pragma unroll
        for (int o = 16; o > 0; o >>= 1) s += __shfl_xor_sync(0xffffffffu, s, o);
        float inv = 1.f / s;
        float prob[3] = { e0 * inv, e1 * inv, e2 * inv };

        const float2* offp = (const float2*)(g_off + (size_t)r * (NH_*PTS_*2) + h * (PTS_*2));
        const float* refr = ref + (size_t)r * (NL_*2);

        #pragma unroll
        for (int j = 0; j < 3; j++) {
            int it = lane + j*32;
            if (it < PTS_) {
                int l = it >> 4;
                float2 o2 = offp[it];
                float px = refr[l*2 + 0] * (float)W_ + o2.x - 0.5f;
                float py = refr[l*2 + 1] * (float)H_ + o2.y - 0.5f;
                float x0f = floorf(px), y0f = floorf(py);
                float fx = px - x0f, fy = py - y0f;
                int x0 = (int)x0f, y0 = (int)y0f;
                float aw = prob[j];
                float w00 = aw*(1.f-fy)*(1.f-fx);
                float w01 = aw*(1.f-fy)*fx;
                float w10 = aw*fy*(1.f-fx);
                float w11 = aw*fy*fx;
                if (!(((unsigned)y0     < (unsigned)H_) && ((unsigned)x0     < (unsigned)W_))) w00 = 0.f;
                if (!(((unsigned)y0     < (unsigned)H_) && ((unsigned)(x0+1) < (unsigned)W_))) w01 = 0.f;
                if (!(((unsigned)(y0+1) < (unsigned)H_) && ((unsigned)x0     < (unsigned)W_))) w10 = 0.f;
                if (!(((unsigned)(y0+1) < (unsigned)H_) && ((unsigned)(x0+1) < (unsigned)W_))) w11 = 0.f;
                int xc0 = min(max(x0,     0), W_-1);
                int xc1 = min(max(x0 + 1, 0), W_-1);
                int yc0 = min(max(y0,     0), H_-1);
                int yc1 = min(max(y0 + 1, 0), H_-1);
                uint32_t lbase = (uint32_t)l << 19;   // level stride = 512 KB
                int cr = it * 4;
                uint2 o01, o23;
                o01.x = lbase + ((uint32_t)(yc0*W_ + xc0) << 6);
                o01.y = lbase + ((uint32_t)(yc0*W_ + xc1) << 6);
                o23.x = lbase + ((uint32_t)(yc1*W_ + xc0) << 6);
                o23.y = lbase + ((uint32_t)(yc1*W_ + xc1) << 6);
                *(uint2*)&s_off[h][cr]     = o01;
                *(uint2*)&s_off[h][cr + 2] = o23;
                __nv_bfloat162 wp0, wp1;
                wp0.x = __float2bfloat16(w00); wp0.y = __float2bfloat16(w01);
                wp1.x = __float2bfloat16(w10); wp1.y = __float2bfloat16(w11);
                *(uint32_t*)&s_w[h][cr]     = *(uint32_t*)&wp0;
                *(uint32_t*)&s_w[h][cr + 2] = *(uint32_t*)&wp1;
            }
        }
    }
    __syncwarp();

    // ---- Phase 2: tensor-core weighted gather ----
    int row  = lane >> 1;          // corner-row within chunk (0-15)
    int part = lane & 1;           // 16B part within first 32B half
    const char* vbase = (const char*)(g_valh
        + (size_t)((b*NL_)*NH_ + h) * (HW_*HD_));
    char* stage0 = (char*)&s_stage[h][0][0];
    uint32_t sts_coff = (uint32_t)row*(STW_*2) + part*16u;

    // ldmatrix.trans per-lane address: matrices (k0-7,n0-7),(k8-15,n0-7),
    // (k0-7,n8-15),(k8-15,n8-15) for the first ldmx4; +32B for chans 16-31.
    int msel = lane >> 3, rim = lane & 7;
    uint32_t lrow = (uint32_t)(((msel & 1) << 3) + rim);
    uint32_t loff = (msel & 2) ? 16u : 0u;
    uint32_t ldm_base = smem_u32(stage0) + lrow*(STW_*2) + loff;

    float d0[4] = {0,0,0,0}, d1[4] = {0,0,0,0};
    float d2[4] = {0,0,0,0}, d3[4] = {0,0,0,0};
    const uint32_t* offrow = s_off[h];
    const __nv_bfloat16* wrow = s_w[h];
    int aidx = 2 * (lane & 3);

    #pragma unroll 2
    for (int c = 0; c < PTS_*4/16; c++) {   // 20 chunks of 16 corner-rows
        uint32_t bofs = (c & 1) ? (uint32_t)STAGE_B_ : 0u;
        uint32_t off = offrow[c*16 + row];
        const char* src = vbase + off + part*16;
        uint4 v0 = *(const uint4*)(src);
        uint4 v1 = *(const uint4*)(src + 32);
        *(uint4*)(stage0 + bofs + sts_coff)      = v0;
        *(uint4*)(stage0 + bofs + sts_coff + 32) = v1;
        __syncwarp();
        uint32_t af[4];
        af[0] = *(const uint32_t*)&wrow[c*16 + aidx];       // A[0][k0-7] pairs
        af[1] = 0u;
        af[2] = *(const uint32_t*)&wrow[c*16 + 8 + aidx];   // A[0][k8-15] pairs
        af[3] = 0u;
        uint32_t b0, b1, b2, b3;
        ldmx4t(b0, b1, b2, b3, ldm_base + bofs);
        { uint32_t bA[2] = {b0, b1}; mma_bf16(d0, af, bA); }
        { uint32_t bB[2] = {b2, b3}; mma_bf16(d1, af, bB); }
        ldmx4t(b0, b1, b2, b3, ldm_base + bofs + 32);
        { uint32_t bC[2] = {b0, b1}; mma_bf16(d2, af, bC); }
        { uint32_t bD[2] = {b2, b3}; mma_bf16(d3, af, bD); }
    }

    // D row 0 lives in lanes 0-3: c0 = D[0][g*8+2t], c1 = D[0][g*8+2t+1]
    if (lane < 4) {
        int base = r*C_ + h*HD_ + 2*lane;
        __nv_bfloat162 o;
        o.x = __float2bfloat16(d0[0]); o.y = __float2bfloat16(d0[1]);
        *(uint32_t*)&g_samp[base + 0]  = *(uint32_t*)&o;
        o.x = __float2bfloat16(d1[0]); o.y = __float2bfloat16(d1[1]);
        *(uint32_t*)&g_samp[base + 8]  = *(uint32_t*)&o;
        o.x = __float2bfloat16(d2[0]); o.y = __float2bfloat16(d2[1]);
        *(uint32_t*)&g_samp[base + 16] = *(uint32_t*)&o;
        o.x = __float2bfloat16(d3[0]); o.y = __float2bfloat16(d3[1]);
        *(uint32_t*)&g_samp[base + 24] = *(uint32_t*)&o;
    }
}

// ---------------------------------------------------------------------------
// Launch
// ---------------------------------------------------------------------------
extern "C" void kernel_launch(void* const* d_in, const int* in_sizes, int n_in,
                              void* d_out, int out_size)
{
    const float* x     = (const float*)d_in[0];
    const float* ref   = (const float*)d_in[1];
    const float* n3g   = (const float*)d_in[4];
    const float* n3b   = (const float*)d_in[5];
    const float* n4g   = (const float*)d_in[6];
    const float* n4b   = (const float*)d_in[7];
    const float* w_off = (const float*)d_in[8];
    const float* b_off = (const float*)d_in[9];
    const float* w_attn= (const float*)d_in[10];
    const float* b_attn= (const float*)d_in[11];
    const float* w_val = (const float*)d_in[12];
    const float* b_val = (const float*)d_in[13];
    const float* w_out = (const float*)d_in[14];
    const float* b_out = (const float*)d_in[15];
    const float* w_fc1 = (const float*)d_in[16];
    const float* b_fc1 = (const float*)d_in[17];
    const float* w_fc2 = (const float*)d_in[18];
    const float* b_fc2 = (const float*)d_in[19];
    float* out = (float*)d_out;

    __nv_bfloat16 *p_q, *p_samp, *p_h, *p_mlp;
    __nv_bfloat16 *p_wproj, *p_wout, *p_wfc1, *p_wfc2;
    cudaGetSymbolAddress((void**)&p_q,    g_q);
    cudaGetSymbolAddress((void**)&p_samp, g_samp);
    cudaGetSymbolAddress((void**)&p_h,    g_h);
    cudaGetSymbolAddress((void**)&p_mlp,  g_mlp);
    cudaGetSymbolAddress((void**)&p_wproj,g_wproj);
    cudaGetSymbolAddress((void**)&p_wout, g_wout);
    cudaGetSymbolAddress((void**)&p_wfc1, g_wfc1);
    cudaGetSymbolAddress((void**)&p_wfc2, g_wfc2);

    tcvt6_kernel<<<1120, dim3(32,32)>>>(
        w_val, w_off, w_attn, w_out, w_fc1, w_fc2,
        p_wproj, p_wout, p_wfc1, p_wfc2);

    // 1) LN3 -> q (bf16)
    ln_kernel<<<M_, 256>>>(x, n3g, n3b, p_q);

    // 2) fused projections: val (head-major bf16) + offsets + attn logits
    gemm_proj<<<dim3(NPROJ_/128, M_/128), 256>>>(p_q, b_val, b_off, b_attn);

    // 3) fused softmax + prep + tensor-core gather -> g_samp (bf16)
    sample_fused_kernel<<<M_, 256>>>(ref);

    // 4) out projection + residual(x) -> d_out (fp32)
    gemm_hmma<0,1,0><<<dim3(C_/128, M_/128), 256>>>(
        M_, C_, C_, p_samp, p_wout, b_out, x, out, nullptr);

    // 5) LN4 -> h (bf16)
    ln_kernel<<<M_, 256>>>(out, n4g, n4b, p_h);

    // 6) fc1 + GELU -> bf16
    gemm_hmma<1,0,1><<<dim3(MLP_H_/128, M_/128), 256>>>(
        M_, MLP_H_, C_, p_h, p_wfc1, b_fc1, nullptr, nullptr, p_mlp);

    // 7) fc2 + residual(d_out) -> d_out (fp32, in-place elementwise-safe)
    gemm_hmma<0,1,0><<<dim3(C_/128, M_/128), 256>>>(
        M_, C_, MLP_H_, p_mlp, p_wfc2, b_fc2, out, out, nullptr);
}